// round 13
// baseline (speedup 1.0000x reference)
#include <cuda_runtime.h>
#include <cuda_fp16.h>
#include <cstdint>

#define SORB  64
#define HID   256
#define BATCH 8192
#define LEN   1056
#define NSTEP 32
#define TB    2      // batch elements per warp

// Byte subset-sum LUT in fp16 (negated, zero for j >= 2m):
//   g_byte[p][byte][m] = half2( -Σ_{b∈byte} u0[8p+b] , -Σ_{b∈byte} u1[8p+b] )
// where u0[j] = Σ_h W[h,start+j]·w0, u1 likewise with w1.  256 KB total.
// g_c12[m]    = ( -Σhb·w0 - 0.5Σw0² , -Σhb·w1 - 0.5Σw1² )
// g_negQ01[m] = -Σ w0·w1
__device__ __half2 g_byte[8][256][32];
__device__ float2  g_c12[32];
__device__ float   g_negQ01[32];

// grid 256 = (m = bid>>3, p = bid&7); 256 threads.
__global__ __launch_bounds__(256)
void precompute_kernel(const float* __restrict__ W, const float* __restrict__ hb)
{
    const int m = blockIdx.x >> 3, p = blockIdx.x & 7;
    const int k = 2 * m, start = m * (m + 1);
    __shared__ float  sw0[HID], sw1[HID];
    __shared__ float  pp0[8][32], pp1[8][32];
    __shared__ float2 su[8];
    const int tid = threadIdx.x;
    const int lane = tid & 31, wid = tid >> 5;

    // stage w0,w1 (strided float2 gather)
    {
        const float2 v = *(const float2*)(W + (size_t)tid * LEN + start + k);
        sw0[tid] = v.x;
        sw1[tid] = v.y;
    }
    __syncthreads();

    // u[j] for j in [8p, 8p+8): thread = (jl = tid&7, grp = tid>>3), 8 h each
    {
        const int jl = tid & 7, grp = tid >> 3;
        const int j = 8 * p + jl;
        float a0 = 0.f, a1 = 0.f;
        if (j < k) {
            const float* pw = W + start + j;
            #pragma unroll
            for (int hh = 0; hh < 8; ++hh) {
                const int h = grp * 8 + hh;
                const float wv = pw[(size_t)h * LEN];
                a0 = fmaf(wv, sw0[h], a0);
                a1 = fmaf(wv, sw1[h], a1);
            }
        }
        pp0[jl][grp] = a0;
        pp1[jl][grp] = a1;
    }
    __syncthreads();

    if (tid < 8) {
        float s0 = 0.f, s1 = 0.f;
        #pragma unroll
        for (int g = 0; g < 32; ++g) { s0 += pp0[tid][g]; s1 += pp1[tid][g]; }
        su[tid] = make_float2(-s0, -s1);
    }
    // constants (once per m, in p==0 blocks)
    if (p == 0 && wid == 2) {                 // -Σ w0·w1
        float acc = 0.f;
        #pragma unroll
        for (int hh = lane; hh < HID; hh += 32)
            acc = fmaf(sw0[hh], sw1[hh], acc);
        acc += __shfl_xor_sync(0xffffffffu, acc, 16);
        acc += __shfl_xor_sync(0xffffffffu, acc, 8);
        acc += __shfl_xor_sync(0xffffffffu, acc, 4);
        acc += __shfl_xor_sync(0xffffffffu, acc, 2);
        acc += __shfl_xor_sync(0xffffffffu, acc, 1);
        if (lane == 0) g_negQ01[m] = -acc;
    }
    if (p == 0 && wid == 7) {                 // L1/L2 bases
        const float* sw = (lane < 16) ? sw0 : sw1;
        const int l2 = lane & 15;
        float ab = 0.f, qq = 0.f;
        #pragma unroll
        for (int hh = l2; hh < HID; hh += 16) {
            const float wv = sw[hh];
            ab = fmaf(hb[hh], wv, ab);
            qq = fmaf(wv, wv, qq);
        }
        #pragma unroll
        for (int s = 8; s >= 1; s >>= 1) {
            ab += __shfl_down_sync(0xffffffffu, ab, s);
            qq += __shfl_down_sync(0xffffffffu, qq, s);
        }
        if (l2 == 0) {
            const float v = -ab - 0.5f * qq;
            if (lane < 16) g_c12[m].x = v; else g_c12[m].y = v;
        }
    }
    __syncthreads();

    // byte subset sums: tid = byte value; store fp16 pair
    {
        float a0 = 0.f, a1 = 0.f;
        #pragma unroll
        for (int b = 0; b < 8; ++b)
            if ((tid >> b) & 1) { const float2 u = su[b]; a0 += u.x; a1 += u.y; }
        g_byte[p][tid][m] = __floats2half2_rn(a0, a1);
    }
}

// exp(L) for |L| <= 0.05, rel err < 5e-8
__device__ __forceinline__ float expq(float L) {
    return fmaf(L, fmaf(L, fmaf(L, 0.16666667f, 0.5f), 1.0f), 1.0f);
}

// 4 warps/block, TB=2 batch elements per warp; lane = step m.
// 16 fp16 byte-LUT loads per warp (1 L1 wavefront each). No smem, no sync.
__global__ __launch_bounds__(128)
void rbm_main_kernel(const int* __restrict__ x, float* __restrict__ out)
{
    const int tid  = threadIdx.x;
    const int lane = tid & 31, wid = tid >> 5;
    const int m    = lane;
    const int k    = 2 * m;

    const int b0 = (blockIdx.x * 4 + wid) * TB;
    unsigned lo[TB], hi[TB];
    #pragma unroll
    for (int t = 0; t < TB; ++t) {
        const int v0 = x[(size_t)(b0 + t) * SORB + lane];
        const int v1 = x[(size_t)(b0 + t) * SORB + 32 + lane];
        lo[t] = __ballot_sync(0xffffffffu, v0 > 0);
        hi[t] = __ballot_sync(0xffffffffu, v1 > 0);
    }

    // Entry address = base + p*32768 + byte*128 + lane*4
    const char* base = (const char*)g_byte + (size_t)lane * sizeof(__half2);

    // All 16 loads issued as one independent batch (MLP = 16)
    __half2 v[8 * TB];
    #pragma unroll
    for (int p = 0; p < 8; ++p) {
        const int sh = p & 3;
        #pragma unroll
        for (int t = 0; t < TB; ++t) {
            const unsigned w   = (p < 4) ? lo[t] : hi[t];
            const unsigned off = (sh == 0) ? ((w << 7) & 0x7F80u)
                                           : ((w >> (8 * sh - 7)) & 0x7F80u);
            v[p * TB + t] = __ldg((const __half2*)(base + (size_t)p * 32768 + off));
        }
    }

    const float2 c12 = __ldg(&g_c12[m]);
    float L1[TB], L2[TB];
    #pragma unroll
    for (int t = 0; t < TB; ++t) {
        L1[t] = c12.x;
        L2[t] = c12.y;
        #pragma unroll
        for (int p = 0; p < 8; ++p) {
            const float2 f = __half22float2(v[p * TB + t]);
            L1[t] += f.x;
            L2[t] += f.y;
        }
    }

    const unsigned mlo = (k >= 32) ? 0xffffffffu : ((1u << k) - 1u);
    const unsigned mhi = (k > 32) ? ((1u << (k - 32)) - 1u) : 0u;
    const float negQ01 = __ldg(&g_negQ01[m]);

    float terms[TB];
    #pragma unroll
    for (int t = 0; t < TB; ++t) {
        const float L3 = L1[t] + L2[t] + negQ01;
        float v0f = 1.f, v1f = expq(L1[t]), v2f = expq(L2[t]), v3f = expq(L3);

        const int nu = __popc(lo[t] & 0x55555555u & mlo) + __popc(hi[t] & 0x55555555u & mhi);
        const int nd = __popc(lo[t] & 0xAAAAAAAAu & mlo) + __popc(hi[t] & 0xAAAAAAAAu & mhi);

        if (m >= 8) {                        // SYMMETRY && alpha_e <= k
            const int lower = m - 16;        // base + k/2
            const bool ou = nu < 16, uu = nu > lower;
            const bool od = nd < 16, ud = nd > lower;
            v0f = (uu && ud) ? v0f : 0.f;
            v1f = (ou && ud) ? v1f : 0.f;
            v2f = (uu && od) ? v2f : 0.f;
            v3f = (ou && od) ? v3f : 0.f;
        }

        const float n2 = v0f*v0f + v1f*v1f + v2f*v2f + v3f*v3f;
        float inv = rsqrtf(fmaxf(n2, 1e-24f));
        inv = inv * fmaf(-0.5f * n2 * inv, inv, 1.5f);   // Newton

        const int bu = (k < 32) ? ((lo[t] >> k) & 1)       : ((hi[t] >> (k - 32)) & 1);
        const int bd = (k < 32) ? ((lo[t] >> (k + 1)) & 1) : ((hi[t] >> (k - 31)) & 1);
        const int st = bu + 2 * bd;
        const float vs = st == 0 ? v0f : st == 1 ? v1f : st == 2 ? v2f : v3f;

        float term = vs * inv;
        term *= __shfl_xor_sync(0xffffffffu, term, 16);
        term *= __shfl_xor_sync(0xffffffffu, term, 8);
        term *= __shfl_xor_sync(0xffffffffu, term, 4);
        term *= __shfl_xor_sync(0xffffffffu, term, 2);
        term *= __shfl_xor_sync(0xffffffffu, term, 1);
        terms[t] = term;
    }

    float o = terms[0];
    #pragma unroll
    for (int t = 1; t < TB; ++t) o = (lane == t) ? terms[t] : o;
    if (lane < TB) out[b0 + lane] = o;
}

extern "C" void kernel_launch(void* const* d_in, const int* in_sizes, int n_in,
                              void* d_out, int out_size)
{
    const int*   x   = (const int*)d_in[0];
    const float* W   = (const float*)d_in[1];
    const float* hb  = (const float*)d_in[2];
    float*       out = (float*)d_out;

    precompute_kernel<<<NSTEP * 8, 256>>>(W, hb);
    rbm_main_kernel<<<BATCH / (4 * TB), 128>>>(x, out);
}

// round 14
// speedup vs baseline: 1.0623x; 1.0623x over previous
#include <cuda_runtime.h>
#include <cstdint>

#define SORB  64
#define HID   256
#define BATCH 8192
#define LEN   1056
#define NSTEP 32
#define TB    4      // batch elements per warp

// Byte subset-sum table fp32 (negated, zero for j >= 2m):
//   g_byte[p][byte][m] = -Σ_{b set in byte} ( Σ_h W[h,start(m)+8p+b]·(w0,w1)^m )
// g_c12[m]    = ( -Σhb·w0 - 0.5Σw0² , -Σhb·w1 - 0.5Σw1² )
// g_negQ01[m] = -Σ w0·w1
__device__ float2 g_byte[8][256][32];
__device__ float2 g_c12[32];
__device__ float  g_negQ01[32];

// grid 128 = (m = bid>>2, q = bid&3); block builds byte positions 2q, 2q+1.
__global__ __launch_bounds__(256)
void precompute_kernel(const float* __restrict__ W, const float* __restrict__ hb)
{
    const int m = blockIdx.x >> 2, q = blockIdx.x & 3;
    const int k = 2 * m, start = m * (m + 1);
    __shared__ float  sw0[HID], sw1[HID];
    __shared__ float  pp0[16][16], pp1[16][16];
    __shared__ float2 su[16];
    const int tid = threadIdx.x;
    const int lane = tid & 31, wid = tid >> 5;

    // stage w0,w1 (strided float2 gather)
    {
        const float2 v = *(const float2*)(W + (size_t)tid * LEN + start + k);
        sw0[tid] = v.x;
        sw1[tid] = v.y;
    }
    __syncthreads();

    // u[j] for j in [16q, 16q+16): thread = (jl = tid&15, grp = tid>>4), 16 h each
    {
        const int jl = tid & 15, grp = tid >> 4;
        const int j = 16 * q + jl;
        float a0 = 0.f, a1 = 0.f;
        if (j < k) {
            const float* pw = W + start + j;
            #pragma unroll
            for (int hh = 0; hh < 16; ++hh) {
                const int h = grp * 16 + hh;
                const float wv = pw[(size_t)h * LEN];
                a0 = fmaf(wv, sw0[h], a0);
                a1 = fmaf(wv, sw1[h], a1);
            }
        }
        pp0[jl][grp] = a0;
        pp1[jl][grp] = a1;
    }
    __syncthreads();

    if (tid < 16) {
        float s0 = 0.f, s1 = 0.f;
        #pragma unroll
        for (int g = 0; g < 16; ++g) { s0 += pp0[tid][g]; s1 += pp1[tid][g]; }
        su[tid] = make_float2(-s0, -s1);
    }
    // constants (once per m, in q==0 blocks)
    if (q == 0 && wid == 2) {                 // -Σ w0·w1
        float acc = 0.f;
        #pragma unroll
        for (int hh = lane; hh < HID; hh += 32)
            acc = fmaf(sw0[hh], sw1[hh], acc);
        acc += __shfl_xor_sync(0xffffffffu, acc, 16);
        acc += __shfl_xor_sync(0xffffffffu, acc, 8);
        acc += __shfl_xor_sync(0xffffffffu, acc, 4);
        acc += __shfl_xor_sync(0xffffffffu, acc, 2);
        acc += __shfl_xor_sync(0xffffffffu, acc, 1);
        if (lane == 0) g_negQ01[m] = -acc;
    }
    if (q == 0 && wid == 7) {                 // L1/L2 bases
        const float* sw = (lane < 16) ? sw0 : sw1;
        const int l2 = lane & 15;
        float ab = 0.f, qq = 0.f;
        #pragma unroll
        for (int hh = l2; hh < HID; hh += 16) {
            const float wv = sw[hh];
            ab = fmaf(hb[hh], wv, ab);
            qq = fmaf(wv, wv, qq);
        }
        #pragma unroll
        for (int s = 8; s >= 1; s >>= 1) {
            ab += __shfl_down_sync(0xffffffffu, ab, s);
            qq += __shfl_down_sync(0xffffffffu, qq, s);
        }
        if (l2 == 0) {
            const float v = -ab - 0.5f * qq;
            if (lane < 16) g_c12[m].x = v; else g_c12[m].y = v;
        }
    }
    __syncthreads();

    // byte subset sums: 512 entries (2 positions), 2 per thread
    #pragma unroll
    for (int e = 0; e < 2; ++e) {
        const int idx = e * 256 + tid;
        const int pl  = idx >> 8;             // 0 or 1
        const int byv = idx & 255;
        float a0 = 0.f, a1 = 0.f;
        #pragma unroll
        for (int b = 0; b < 8; ++b)
            if ((byv >> b) & 1) { const float2 u = su[pl * 8 + b]; a0 += u.x; a1 += u.y; }
        g_byte[2 * q + pl][byv][m] = make_float2(a0, a1);
    }
}

// exp(L) for |L| <= 0.05, rel err < 5e-8
__device__ __forceinline__ float expq(float L) {
    return fmaf(L, fmaf(L, fmaf(L, 0.16666667f, 0.5f), 1.0f), 1.0f);
}

// 4 warps/block, TB=4 batch elements per warp; lane = step m.
// 32 fp32 byte-LUT loads per warp, single independent batch (MLP=32).
__global__ __launch_bounds__(128)
void rbm_main_kernel(const int* __restrict__ x, float* __restrict__ out)
{
    const int tid  = threadIdx.x;
    const int lane = tid & 31, wid = tid >> 5;
    const int m    = lane;
    const int k    = 2 * m;

    const int b0 = (blockIdx.x * 4 + wid) * TB;
    unsigned lo[TB], hi[TB];
    #pragma unroll
    for (int t = 0; t < TB; ++t) {
        const int v0 = x[(size_t)(b0 + t) * SORB + lane];
        const int v1 = x[(size_t)(b0 + t) * SORB + 32 + lane];
        lo[t] = __ballot_sync(0xffffffffu, v0 > 0);
        hi[t] = __ballot_sync(0xffffffffu, v1 > 0);
    }

    // Entry address = base + p*65536 + byte*256 + lane*8
    const char* base = (const char*)g_byte + (size_t)lane * sizeof(float2);

    // All 32 loads issued as one independent batch
    float2 v[8 * TB];
    #pragma unroll
    for (int p = 0; p < 8; ++p) {
        const int sh = p & 3;
        #pragma unroll
        for (int t = 0; t < TB; ++t) {
            const unsigned w   = (p < 4) ? lo[t] : hi[t];
            const unsigned off = (sh == 0) ? ((w << 8) & 0xFF00u)
                                           : ((w >> (8 * sh - 8)) & 0xFF00u);
            v[p * TB + t] = __ldg((const float2*)(base + (size_t)p * 65536 + off));
        }
    }

    const float2 c12 = __ldg(&g_c12[m]);
    float L1[TB], L2[TB];
    #pragma unroll
    for (int t = 0; t < TB; ++t) {
        L1[t] = c12.x;
        L2[t] = c12.y;
        #pragma unroll
        for (int p = 0; p < 8; ++p) {
            L1[t] += v[p * TB + t].x;
            L2[t] += v[p * TB + t].y;
        }
    }

    const unsigned mlo = (k >= 32) ? 0xffffffffu : ((1u << k) - 1u);
    const unsigned mhi = (k > 32) ? ((1u << (k - 32)) - 1u) : 0u;
    const float negQ01 = __ldg(&g_negQ01[m]);

    float terms[TB];
    #pragma unroll
    for (int t = 0; t < TB; ++t) {
        const float L3 = L1[t] + L2[t] + negQ01;
        float v0f = 1.f, v1f = expq(L1[t]), v2f = expq(L2[t]), v3f = expq(L3);

        const int nu = __popc(lo[t] & 0x55555555u & mlo) + __popc(hi[t] & 0x55555555u & mhi);
        const int nd = __popc(lo[t] & 0xAAAAAAAAu & mlo) + __popc(hi[t] & 0xAAAAAAAAu & mhi);

        if (m >= 8) {                        // SYMMETRY && alpha_e <= k
            const int lower = m - 16;        // base + k/2
            const bool ou = nu < 16, uu = nu > lower;
            const bool od = nd < 16, ud = nd > lower;
            v0f = (uu && ud) ? v0f : 0.f;
            v1f = (ou && ud) ? v1f : 0.f;
            v2f = (uu && od) ? v2f : 0.f;
            v3f = (ou && od) ? v3f : 0.f;
        }

        const float n2 = v0f*v0f + v1f*v1f + v2f*v2f + v3f*v3f;
        float inv = rsqrtf(fmaxf(n2, 1e-24f));
        inv = inv * fmaf(-0.5f * n2 * inv, inv, 1.5f);   // Newton

        const int bu = (k < 32) ? ((lo[t] >> k) & 1)       : ((hi[t] >> (k - 32)) & 1);
        const int bd = (k < 32) ? ((lo[t] >> (k + 1)) & 1) : ((hi[t] >> (k - 31)) & 1);
        const int st = bu + 2 * bd;
        const float vs = st == 0 ? v0f : st == 1 ? v1f : st == 2 ? v2f : v3f;

        float term = vs * inv;
        term *= __shfl_xor_sync(0xffffffffu, term, 16);
        term *= __shfl_xor_sync(0xffffffffu, term, 8);
        term *= __shfl_xor_sync(0xffffffffu, term, 4);
        term *= __shfl_xor_sync(0xffffffffu, term, 2);
        term *= __shfl_xor_sync(0xffffffffu, term, 1);
        terms[t] = term;
    }

    float o = terms[0];
    #pragma unroll
    for (int t = 1; t < TB; ++t) o = (lane == t) ? terms[t] : o;
    if (lane < TB) out[b0 + lane] = o;
}

extern "C" void kernel_launch(void* const* d_in, const int* in_sizes, int n_in,
                              void* d_out, int out_size)
{
    const int*   x   = (const int*)d_in[0];
    const float* W   = (const float*)d_in[1];
    const float* hb  = (const float*)d_in[2];
    float*       out = (float*)d_out;

    precompute_kernel<<<NSTEP * 4, 256>>>(W, hb);
    rbm_main_kernel<<<BATCH / (4 * TB), 128>>>(x, out);
}